// round 1
// baseline (speedup 1.0000x reference)
#include <cuda_runtime.h>

// linear_sig: depth-3 path signature (B=2048, T=128, C=8) + linear head (584 -> 10)
//
// One warp per batch row. Lane r owns level-2/3 slices for i = r>>2,
// j in {2*(r&3), 2*(r&3)+1}:  2 S2 scalars + 16 S3 registers.
// Update rules (old state on RHS):
//   u = dx_i/6 + S1_i/2 ; v = dx_i/2 + S1_i
//   t3_j = dx_j*u + S2_ij ;  S3[i,j,l] += t3_j * dx_l
//   S2_ij += dx_j * v      ;  S1_i += dx_i
// X rows are staged through double-buffered shared memory (32 rows/chunk)
// so the sequential 32B/step stream never exposes DRAM latency.
// Epilogue: W re-laid out in shared with stride 19 (conflict-free), warp
// shuffle-reduce per output.

constexpr int TT      = 128;
constexpr int CC      = 8;
constexpr int NOUT    = 10;
constexpr int SIGDIM  = 584;   // 8 + 64 + 512
constexpr int WARPS   = 8;
constexpr int THREADS = WARPS * 32;
constexpr int CHUNK   = 32;          // rows staged per chunk
constexpr int NCHUNK  = TT / CHUNK;  // 4

__global__ __launch_bounds__(THREADS, 2)
void sig_linear_kernel(const float* __restrict__ X,
                       const float* __restrict__ W,
                       const float* __restrict__ Bv,
                       float* __restrict__ out, int nB)
{
    __shared__ __align__(16) float sW2[NOUT * 32 * 19];  // reordered W, stride 19
    __shared__ float sb[NOUT];
    __shared__ __align__(16) float sx[WARPS][2][CHUNK * CC];

    // Build reordered W: sW2[n][lane][k]
    //   k=0,1   -> W[n, 8 + 2*lane + k]            (S2 pair)
    //   k=2..17 -> W[n, 72 + 16*lane + (k-2)]      (S3 block)
    //   k=18    -> (lane%4==0) ? W[n, lane/4] : 0  (S1, dedup across replicas)
    for (int idx = threadIdx.x; idx < NOUT * 32 * 19; idx += THREADS) {
        int n   = idx / (32 * 19);
        int rem = idx - n * (32 * 19);
        int r   = rem / 19;
        int k   = rem - r * 19;
        const float* Wn = W + n * SIGDIM;
        float v;
        if (k < 2)       v = Wn[8 + 2 * r + k];
        else if (k < 18) v = Wn[72 + 16 * r + (k - 2)];
        else             v = ((r & 3) == 0) ? Wn[r >> 2] : 0.0f;
        sW2[idx] = v;
    }
    if (threadIdx.x < NOUT) sb[threadIdx.x] = Bv[threadIdx.x];
    __syncthreads();

    const int wib  = threadIdx.x >> 5;
    const int lane = threadIdx.x & 31;
    const int gw   = blockIdx.x * WARPS + wib;
    if (gw >= nB) return;

    const float* xb = X + (size_t)gw * (TT * CC);
    const int i0 = lane >> 2;          // owned i channel
    const int j0 = (lane & 3) << 1;    // owned j pair start (even)

    float S1i = 0.f, S20 = 0.f, S21 = 0.f;
    float S3[16];
    #pragma unroll
    for (int k = 0; k < 16; k++) S3[k] = 0.f;

    // Stage chunk 0 (each lane loads one 8-float row, coalesced)
    {
        float4 a = *(const float4*)(xb + lane * 8);
        float4 c = *(const float4*)(xb + lane * 8 + 4);
        *(float4*)(&sx[wib][0][lane * 8])     = a;
        *(float4*)(&sx[wib][0][lane * 8 + 4]) = c;
    }
    __syncwarp();

    // prev = row 0
    float4 xpA = *(const float4*)(&sx[wib][0][0]);
    float4 xpB = *(const float4*)(&sx[wib][0][4]);
    float  xpi = sx[wib][0][i0];
    float2 xpj = *(const float2*)(&sx[wib][0][j0]);

    int cur = 0;
    for (int c = 0; c < NCHUNK; c++) {
        // Prefetch next chunk into registers (latency overlapped with compute)
        float4 nx0, nx1;
        if (c + 1 < NCHUNK) {
            const float* src = xb + (c + 1) * (CHUNK * CC) + lane * 8;
            nx0 = *(const float4*)(src);
            nx1 = *(const float4*)(src + 4);
        }
        const float* buf = sx[wib][cur];
        int s0 = (c == 0) ? 1 : 0;
        #pragma unroll 4
        for (int s = s0; s < CHUNK; s++) {
            const float* row = buf + s * CC;
            float4 xnA = *(const float4*)(row);       // broadcast LDS.128
            float4 xnB = *(const float4*)(row + 4);
            float  xni = row[i0];                      // lane-selected (no reg indexing)
            float2 xnj = *(const float2*)(row + j0);

            float dx0 = xnA.x - xpA.x, dx1 = xnA.y - xpA.y;
            float dx2 = xnA.z - xpA.z, dx3 = xnA.w - xpA.w;
            float dx4 = xnB.x - xpB.x, dx5 = xnB.y - xpB.y;
            float dx6 = xnB.z - xpB.z, dx7 = xnB.w - xpB.w;
            float dxi  = xni - xpi;
            float dxj0 = xnj.x - xpj.x;
            float dxj1 = xnj.y - xpj.y;
            xpA = xnA; xpB = xnB; xpi = xni; xpj = xnj;

            float u   = dxi * (1.f/6.f) + S1i * 0.5f;   // old S1
            float v   = dxi * 0.5f + S1i;
            float t30 = dxj0 * u + S20;                 // old S2
            float t31 = dxj1 * u + S21;

            S3[0]  += t30 * dx0;  S3[1]  += t30 * dx1;
            S3[2]  += t30 * dx2;  S3[3]  += t30 * dx3;
            S3[4]  += t30 * dx4;  S3[5]  += t30 * dx5;
            S3[6]  += t30 * dx6;  S3[7]  += t30 * dx7;
            S3[8]  += t31 * dx0;  S3[9]  += t31 * dx1;
            S3[10] += t31 * dx2;  S3[11] += t31 * dx3;
            S3[12] += t31 * dx4;  S3[13] += t31 * dx5;
            S3[14] += t31 * dx6;  S3[15] += t31 * dx7;

            S20 += dxj0 * v;
            S21 += dxj1 * v;
            S1i += dxi;
        }
        if (c + 1 < NCHUNK) {
            float* dst = &sx[wib][cur ^ 1][lane * 8];
            *(float4*)(dst)     = nx0;
            *(float4*)(dst + 4) = nx1;
            __syncwarp();
            cur ^= 1;
        }
    }

    // Epilogue: out[gw, n] = b[n] + <sig, W[n]>
    float* orow = out + (size_t)gw * NOUT;
    #pragma unroll
    for (int n = 0; n < NOUT; n++) {
        const float* wn = sW2 + n * (32 * 19) + lane * 19;   // stride 19: conflict-free
        float p = S20 * wn[0] + S21 * wn[1] + S1i * wn[18];
        #pragma unroll
        for (int k = 0; k < 16; k++) p += S3[k] * wn[2 + k];
        #pragma unroll
        for (int off = 16; off; off >>= 1)
            p += __shfl_xor_sync(0xffffffffu, p, off);
        if (lane == 0) orow[n] = p + sb[n];
    }
}

extern "C" void kernel_launch(void* const* d_in, const int* in_sizes, int n_in,
                              void* d_out, int out_size) {
    const float* X  = (const float*)d_in[0];
    const float* W  = (const float*)d_in[1];
    const float* b  = (const float*)d_in[2];
    float* out      = (float*)d_out;
    int nB = in_sizes[0] / (TT * CC);            // 2048
    int grid = (nB + WARPS - 1) / WARPS;         // 256 blocks
    sig_linear_kernel<<<grid, THREADS>>>(X, W, b, out, nB);
}